// round 9
// baseline (speedup 1.0000x reference)
#include <cuda_runtime.h>
#include <cstdint>

#define CAND   512          // candidate buffer entries (u64)
#define TBL    2048         // bins per table
#define XSCALE 102.4f       // TBL / 20  (range [-10, 10])
#define XOFF   1024.0f      // 10 * XSCALE
#define THRESH0 2.7f        // prefilter threshold (fallback makes any value correct)
#define FULLM  0xFFFFFFFFu
#define CH     1024         // elements per pipeline chunk (4KB per array)
#define DEPTH  3            // pipeline stages

static __device__ float g_rowsum[8192];
static __device__ float g_table[2 * TBL];          // [0..TBL)=f_neg, [TBL..2TBL)=f_pos
static __device__ unsigned char g_catbit[16384];   // (1<<(cat-1))&7
static __device__ int   g_count = 0;

// ---------------------------------------------------------------------------
__device__ __forceinline__ unsigned su32(const void* p) {
    return (unsigned)__cvta_generic_to_shared(p);
}
__device__ __forceinline__ unsigned sortkey32(float x) {
    unsigned u = __float_as_uint(x);
    return u ^ ((unsigned)(((int)u) >> 31) | 0x80000000u);
}
__device__ __forceinline__ unsigned long long makekey(unsigned k32, int c) {
    return ((unsigned long long)k32 << 32) |
           (unsigned long long)(0xFFFFFFFFu - (unsigned)c);
}
__device__ __forceinline__ int tbl_idx(float xv) {
    float fx = fmaf(xv, XSCALE, XOFF);
    fx = fminf(fx, 2047.0f);
    fx = fmaxf(fx, 0.0f);
    return (int)fx;
}

__device__ __forceinline__ void mbar_init(unsigned mb, unsigned cnt) {
    asm volatile("mbarrier.init.shared.b64 [%0], %1;" :: "r"(mb), "r"(cnt) : "memory");
}
__device__ __forceinline__ void mbar_expect_tx(unsigned mb, unsigned tx) {
    asm volatile("mbarrier.arrive.expect_tx.shared.b64 _, [%0], %1;"
                 :: "r"(mb), "r"(tx) : "memory");
}
__device__ __forceinline__ void mbar_wait(unsigned mb, unsigned ph) {
    unsigned done = 0;
    while (!done) {
        asm volatile(
            "{\n\t.reg .pred p;\n\t"
            "mbarrier.try_wait.parity.acquire.cta.shared::cta.b64 p, [%1], %2, 0x989680;\n\t"
            "selp.b32 %0, 1, 0, p;\n\t}"
            : "=r"(done) : "r"(mb), "r"(ph) : "memory");
    }
}
__device__ __forceinline__ void bulk_ld(unsigned dst_smem, const void* src, unsigned nb, unsigned mb) {
    asm volatile(
        "cp.async.bulk.shared::cluster.global.mbarrier::complete_tx::bytes [%0], [%1], %2, [%3];"
        :: "r"(dst_smem), "l"(src), "r"(nb), "r"(mb) : "memory");
}
__device__ __forceinline__ void fence_async_smem() {
    asm volatile("fence.proxy.async.shared::cta;" ::: "memory");
}

// ---------------------------------------------------------------------------
// Kernel 0: build loss tables (exact math) + catbit LUT.
// ---------------------------------------------------------------------------
__global__ void asl_build(const int* __restrict__ cat, int C)
{
    int j = blockIdx.x * 256 + threadIdx.x;
    if (j < 2 * TBL) {
        bool pos = j >= TBL;
        int  q   = pos ? j - TBL : j;
        float x  = (q + 0.5f) * (20.0f / TBL) - 10.0f;
        float sp = 1.0f / (1.0f + expf(-x));
        float v;
        if (pos) {
            v = logf(fmaxf(sp, 1e-8f)) * (1.0f - sp);
        } else {
            float pv = fminf(1.05f - sp, 1.0f);
            float om = 1.0f - pv;
            float om2 = om * om;
            v = logf(fmaxf(pv, 1e-8f)) * om2 * om2;
        }
        g_table[j] = v;
    }
    int c = j - 2 * TBL;
    if (c >= 0 && c < C)
        g_catbit[c] = (unsigned char)((1 << (cat[c] - 1)) & 7);
}

// ---------------------------------------------------------------------------
// Kernel 1: one block per row; TMA-1D producer pipeline + table consumer.
// ---------------------------------------------------------------------------
__global__ void __launch_bounds__(256, 5)
asl_row_kernel(const float* __restrict__ X,
               const float* __restrict__ Y,
               const int*   __restrict__ cat,
               const unsigned char* __restrict__ inmap,
               int C, int B, float* __restrict__ out)
{
    const int row  = blockIdx.x;
    const int tid  = threadIdx.x;
    const int lane = tid & 31;
    const int warp = tid >> 5;

    const size_t base = (size_t)row * (size_t)C;
    const float* __restrict__ xr = X + base;
    const float* __restrict__ yr = Y + base;

    __shared__ float s_tbl[2 * TBL];                       // 16 KB
    __shared__ __align__(16) float s_x[DEPTH][CH];         // 12 KB
    __shared__ __align__(16) float s_y[DEPTH][CH];         // 12 KB
    __shared__ unsigned long long s_buf[CAND];             // 4 KB
    __shared__ __align__(8) unsigned long long s_mbar[DEPTH];
    __shared__ unsigned long long s_top[10];
    __shared__ float s_sumw[8];
    __shared__ int s_flags, s_cnt, s_last;

    {   // table L2 -> smem
        const float4* gt = (const float4*)g_table;
        float4* st = (float4*)s_tbl;
#pragma unroll
        for (int i = tid; i < (2 * TBL) / 4; i += 256) st[i] = gt[i];
    }
    if (tid == 0) {
        s_flags = 0; s_cnt = 0;
#pragma unroll
        for (int s = 0; s < DEPTH; ++s) mbar_init(su32(&s_mbar[s]), 1);
    }
    __syncthreads();

    // alignment frame: d = misalignment of row base in floats; xa/ya 16B-aligned
    const int d = (int)(base & 3);
    const float* xa = xr - d;
    const float* ya = yr - d;
    const int Lcap = (d + C + 3) & ~3;              // floats to copy (16B multiple)
    const int nch  = (Lcap + CH - 1) / CH;

    auto issue = [&](int k, int s) {
        const int off = k * CH;
        const unsigned nb = (unsigned)(min(CH, Lcap - off) * 4);
        const unsigned mb = su32(&s_mbar[s]);
        mbar_expect_tx(mb, 2u * nb);
        bulk_ld(su32(&s_x[s][0]), xa + off, nb, mb);
        bulk_ld(su32(&s_y[s][0]), ya + off, nb, mb);
    };

    if (tid == 0) {
        fence_async_smem();
        for (int k = 0; k < DEPTH && k < nch; ++k) issue(k, k);
    }

    float sum = 0.0f;
    int flags = 0;

    int stage = 0, phase = 0;
    for (int k = 0; k < nch; ++k) {
        mbar_wait(su32(&s_mbar[stage]), (unsigned)phase);

        const int goff = k * CH - d;                 // global idx of stage slot 0
        const bool guard = (goff < 0) || (goff + CH > C);

        if (!guard) {
            const int i = tid << 2;
            const float4 xq = *reinterpret_cast<const float4*>(&s_x[stage][i]);
            const float4 yq = *reinterpret_cast<const float4*>(&s_y[stage][i]);

            // unconditional neg-table sums
            sum += s_tbl[tbl_idx(xq.x)];
            sum += s_tbl[tbl_idx(xq.y)];
            sum += s_tbl[tbl_idx(xq.z)];
            sum += s_tbl[tbl_idx(xq.w)];

            const float xm = fmaxf(fmaxf(xq.x, xq.y), fmaxf(xq.z, xq.w));
            if (xm > THRESH0) {
                const int c0 = goff + i;
                if (xq.x > THRESH0) { int q = atomicAdd(&s_cnt, 1); if (q < CAND) s_buf[q] = makekey(sortkey32(xq.x), c0 + 0); }
                if (xq.y > THRESH0) { int q = atomicAdd(&s_cnt, 1); if (q < CAND) s_buf[q] = makekey(sortkey32(xq.y), c0 + 1); }
                if (xq.z > THRESH0) { int q = atomicAdd(&s_cnt, 1); if (q < CAND) s_buf[q] = makekey(sortkey32(xq.z), c0 + 2); }
                if (xq.w > THRESH0) { int q = atomicAdd(&s_cnt, 1); if (q < CAND) s_buf[q] = makekey(sortkey32(xq.w), c0 + 3); }
            }
            const float ym = fmaxf(fmaxf(yq.x, yq.y), fmaxf(yq.z, yq.w));
            if (ym != 0.0f) {
                const int c0 = goff + i;
                if (yq.x != 0.0f) { int j = tbl_idx(xq.x); sum += s_tbl[j + TBL] - s_tbl[j]; flags |= g_catbit[c0 + 0]; }
                if (yq.y != 0.0f) { int j = tbl_idx(xq.y); sum += s_tbl[j + TBL] - s_tbl[j]; flags |= g_catbit[c0 + 1]; }
                if (yq.z != 0.0f) { int j = tbl_idx(xq.z); sum += s_tbl[j + TBL] - s_tbl[j]; flags |= g_catbit[c0 + 2]; }
                if (yq.w != 0.0f) { int j = tbl_idx(xq.w); sum += s_tbl[j + TBL] - s_tbl[j]; flags |= g_catbit[c0 + 3]; }
            }
        } else {
            for (int i = tid; i < CH; i += 256) {
                const int c = goff + i;
                if (c < 0 || c >= C) continue;
                const float xv = s_x[stage][i];
                const float yv = s_y[stage][i];
                const int j = tbl_idx(xv);
                sum += s_tbl[j];
                if (yv != 0.0f) { sum += s_tbl[j + TBL] - s_tbl[j]; flags |= g_catbit[c]; }
                if (xv > THRESH0) {
                    int q = atomicAdd(&s_cnt, 1);
                    if (q < CAND) s_buf[q] = makekey(sortkey32(xv), c);
                }
            }
        }

        __syncthreads();                              // stage fully consumed
        if (tid == 0) {
            const int kn = k + DEPTH;
            if (kn < nch) { fence_async_smem(); issue(kn, stage); }
        }
        if (++stage == DEPTH) { stage = 0; phase ^= 1; }
    }

    // ---- reduce sum & flags ----
#pragma unroll
    for (int off = 16; off; off >>= 1) {
        sum   += __shfl_down_sync(FULLM, sum, off);
        flags |= __shfl_down_sync(FULLM, flags, off);
    }
    if (lane == 0) { s_sumw[warp] = sum; atomicOr(&s_flags, flags); }
    __syncthreads();

    // ---- resolve exact top-10 (fast path: 10 <= n <= CAND on first try) ----
    float thF = THRESH0;
    unsigned long long thK = 0ULL;
    bool useKey = false;
    int iter = 0;
    for (;;) {
        const int n = s_cnt;
        const bool done = (n >= 10 && n <= CAND) || iter >= 32;
        if (done || n > CAND) {
            if (warp == 0) {
                const int m = min(n, CAND);
                for (int kk = 0; kk < 10; ++kk) {
                    unsigned long long v = 0ULL;
                    for (int i = lane; i < m; i += 32) {
                        unsigned long long b = s_buf[i];
                        if (b > v) v = b;
                    }
#pragma unroll
                    for (int off = 16; off; off >>= 1) {
                        unsigned long long o = __shfl_down_sync(FULLM, v, off);
                        if (o > v) v = o;
                    }
                    unsigned long long w = __shfl_sync(FULLM, v, 0);
                    if (lane == 0) s_top[kk] = w;
                    for (int i = lane; i < m; i += 32)
                        if (s_buf[i] == w) s_buf[i] = 0ULL;
                }
            }
            __syncthreads();
            if (done) break;
            thK = s_top[9];
            useKey = true;        // recollect with key >= thK (>=10 guaranteed)
        } else {
            thF -= 4.0f;          // too few: lower the float threshold
            useKey = false;
        }
        __syncthreads();
        if (tid == 0) s_cnt = 0;
        __syncthreads();
        for (int c = tid; c < C; c += 256) {
            const float xv = xr[c];
            if (useKey) {
                unsigned long long key = makekey(sortkey32(xv), c);
                if (key >= thK) {
                    int q = atomicAdd(&s_cnt, 1);
                    if (q < CAND) s_buf[q] = key;
                }
            } else if (xv > thF) {
                int q = atomicAdd(&s_cnt, 1);
                if (q < CAND) s_buf[q] = makekey(sortkey32(xv), c);
            }
        }
        __syncthreads();
        ++iter;
    }

    // ---- correction for the top-10 elements (exact math) ----
    const int fl = s_flags;
    const bool p1 = (fl & 1) != 0, p2 = (fl & 2) != 0, p3 = (fl & 4) != 0;
    const bool has4 = !(p1 | p2 | p3);

    float delta = 0.0f;
    if (tid < 10 && s_top[tid] != 0ULL) {
        const unsigned idx = 0xFFFFFFFFu - (unsigned)(s_top[tid] & 0xFFFFFFFFull);
        const float xv = xr[idx];
        const float yv = yr[idx];
        const float sp = __fdividef(1.0f, 1.0f + __expf(-xv));
        const float sn = fminf(1.05f - sp, 1.0f);
        const bool  pos = (yv != 0.0f);
        const float pv  = pos ? sp : sn;
        const float l   = __logf(fmaxf(pv, 1e-8f));
        const float om  = 1.0f - pv;
        const float om2 = om * om;
        const float w   = pos ? om : om2 * om2;

        const int  cv  = cat[idx];
        const bool inm = inmap[idx] != 0;
        const bool condA = (!inm) && has4;
        const bool condB = (cv == 1 && p1) || (cv == 2 && p2) ||
                           (cv == 3 && p3) || (cv == 4 && has4);
        if (condA || condB) {
            const float factor = (pos ? sn : sp) * 2.0f;   // ALPHA3 = 2
            delta = l * w * (factor - 1.0f);
        }
    }
    if (warp == 0) {
#pragma unroll
        for (int off = 16; off; off >>= 1)
            delta += __shfl_down_sync(FULLM, delta, off);
    }
    if (tid == 0) {
        float tot = delta;
#pragma unroll
        for (int i = 0; i < 8; ++i) tot += s_sumw[i];
        g_rowsum[row] = tot;
    }

    // ---- last-block finalize: deterministic double reduction ----
    __threadfence();
    if (tid == 0) s_last = (atomicAdd(&g_count, 1) == gridDim.x - 1) ? 1 : 0;
    __syncthreads();
    if (s_last) {
        __threadfence();
        double* sd = (double*)s_buf;
        double acc = 0.0;
        for (int i = tid; i < B; i += 256) acc += (double)g_rowsum[i];
        sd[tid] = acc;
        __syncthreads();
#pragma unroll
        for (int off = 128; off; off >>= 1) {
            if (tid < off) sd[tid] += sd[tid + off];
            __syncthreads();
        }
        if (tid == 0) { out[0] = -(float)sd[0]; g_count = 0; }
    }
}

extern "C" void kernel_launch(void* const* d_in, const int* in_sizes, int n_in,
                              void* d_out, int out_size)
{
    const float*         X   = (const float*)d_in[0];
    const float*         Y   = (const float*)d_in[1];
    const int*           cat = (const int*)d_in[2];
    const unsigned char* inm = (const unsigned char*)d_in[3];

    const int C = in_sizes[2];        // per-class arrays -> 9605
    const int B = in_sizes[0] / C;    // 2048

    asl_build<<<(2 * TBL + C + 255) / 256, 256>>>(cat, C);
    asl_row_kernel<<<B, 256>>>(X, Y, cat, inm, C, B, (float*)d_out);
}

// round 10
// speedup vs baseline: 1.0559x; 1.0559x over previous
#include <cuda_runtime.h>
#include <cstdint>

#define CAND 512           // candidate buffer entries (u64)
#define TBL  2048          // bins per table
#define XSCALE 102.4f      // TBL / 20  (range [-10, 10])
#define XOFF   1024.0f     // 10 * XSCALE
#define THRESH0 2.7f       // prefilter threshold (fallback makes any value correct)
#define FULLM 0xFFFFFFFFu

static __device__ float g_rowsum[8192];
static __device__ float g_table[2 * TBL];          // [0..TBL)=f_neg, [TBL..2TBL)=f_pos
static __device__ unsigned char g_catbit[16384];   // (1<<(cat-1))&7
static __device__ int   g_count = 0;

// ---------------------------------------------------------------------------
__device__ __forceinline__ unsigned sortkey32(float x) {
    unsigned u = __float_as_uint(x);
    return u ^ ((unsigned)(((int)u) >> 31) | 0x80000000u);
}
__device__ __forceinline__ unsigned long long makekey(unsigned k32, int c) {
    return ((unsigned long long)k32 << 32) |
           (unsigned long long)(0xFFFFFFFFu - (unsigned)c);
}
__device__ __forceinline__ int tbl_idx(float xv) {
    float fx = fmaf(xv, XSCALE, XOFF);
    fx = fminf(fx, 2047.0f);
    fx = fmaxf(fx, 0.0f);
    return (int)fx;
}

// ---------------------------------------------------------------------------
// Kernel 0: build loss tables (exact math) + catbit LUT.
// ---------------------------------------------------------------------------
__global__ void asl_build(const int* __restrict__ cat, int C)
{
    int j = blockIdx.x * 256 + threadIdx.x;
    if (j < 2 * TBL) {
        bool pos = j >= TBL;
        int  q   = pos ? j - TBL : j;
        float x  = (q + 0.5f) * (20.0f / TBL) - 10.0f;
        float sp = 1.0f / (1.0f + expf(-x));
        float v;
        if (pos) {
            v = logf(fmaxf(sp, 1e-8f)) * (1.0f - sp);
        } else {
            float pv = fminf(1.05f - sp, 1.0f);
            float om = 1.0f - pv;
            float om2 = om * om;
            v = logf(fmaxf(pv, 1e-8f)) * om2 * om2;
        }
        g_table[j] = v;
    }
    int c = j - 2 * TBL;
    if (c >= 0 && c < C)
        g_catbit[c] = (unsigned char)((1 << (cat[c] - 1)) & 7);
}

// ---------------------------------------------------------------------------
// Kernel 1: one block per row.
// ---------------------------------------------------------------------------
__global__ void __launch_bounds__(256, 5)
asl_row_kernel(const float* __restrict__ X,
               const float* __restrict__ Y,
               const int*   __restrict__ cat,
               const unsigned char* __restrict__ inmap,
               int C, int B, float* __restrict__ out)
{
    const int row  = blockIdx.x;
    const int tid  = threadIdx.x;
    const int lane = tid & 31;
    const int warp = tid >> 5;

    const float* __restrict__ xr = X + (size_t)row * C;
    const float* __restrict__ yr = Y + (size_t)row * C;

    __shared__ float s_tbl[2 * TBL];              // 16 KB
    __shared__ unsigned long long s_buf[CAND];    // 4 KB
    __shared__ unsigned long long s_top[10];
    __shared__ float s_sumw[8];
    __shared__ int s_flags, s_cnt, s_last;

    {   // table L2 -> smem
        const float4* gt = (const float4*)g_table;
        float4* st = (float4*)s_tbl;
#pragma unroll
        for (int i = tid; i < (2 * TBL) / 4; i += 256) st[i] = gt[i];
    }
    if (tid == 0) { s_flags = 0; s_cnt = 0; }
    __syncthreads();

    float sum0 = 0.0f, sum1 = 0.0f;
    int flags = 0;

    // alignment: first element index whose address is 16B aligned
    const int p = (int)((4 - (((size_t)row * (size_t)C) & 3)) & 3);
    const int nv = (C - p) >> 2;
    const int t0 = p + (nv << 2);

    // prologue + tail (<=3 elements each)
    for (int c = tid; c < p; c += 256) {
        const float xv = xr[c], yv = yr[c];
        const int j = tbl_idx(xv);
        sum0 += s_tbl[j];
        if (yv != 0.0f) { sum0 += s_tbl[j + TBL] - s_tbl[j]; flags |= g_catbit[c]; }
        if (xv > THRESH0) {
            int q = atomicAdd(&s_cnt, 1);
            if (q < CAND) s_buf[q] = makekey(sortkey32(xv), c);
        }
    }
    for (int c = t0 + tid; c < C; c += 256) {
        const float xv = xr[c], yv = yr[c];
        const int j = tbl_idx(xv);
        sum0 += s_tbl[j];
        if (yv != 0.0f) { sum0 += s_tbl[j + TBL] - s_tbl[j]; flags |= g_catbit[c]; }
        if (xv > THRESH0) {
            int q = atomicAdd(&s_cnt, 1);
            if (q < CAND) s_buf[q] = makekey(sortkey32(xv), c);
        }
    }

    const float4* __restrict__ x4 = (const float4*)(xr + p);
    const float4* __restrict__ y4 = (const float4*)(yr + p);

    // ---- main loop: two unconditional quads, loads batched at loop top ----
    // For v0 < nv2 with tid < 256: v1 = v0+256 <= nv2-1, always valid.
    const int nv2 = nv & ~511;
    for (int v0 = tid; v0 < nv2; v0 += 512) {
        const int v1 = v0 + 256;
        const float4 xa = x4[v0];
        const float4 xb = x4[v1];
        const float4 ya = y4[v0];
        const float4 yb = y4[v1];

        sum0 += s_tbl[tbl_idx(xa.x)];
        sum0 += s_tbl[tbl_idx(xa.y)];
        sum0 += s_tbl[tbl_idx(xa.z)];
        sum0 += s_tbl[tbl_idx(xa.w)];
        sum1 += s_tbl[tbl_idx(xb.x)];
        sum1 += s_tbl[tbl_idx(xb.y)];
        sum1 += s_tbl[tbl_idx(xb.z)];
        sum1 += s_tbl[tbl_idx(xb.w)];

        const float xm = fmaxf(fmaxf(fmaxf(xa.x, xa.y), fmaxf(xa.z, xa.w)),
                               fmaxf(fmaxf(xb.x, xb.y), fmaxf(xb.z, xb.w)));
        if (xm > THRESH0) {
            const int ca = p + (v0 << 2);
            const int cb = p + (v1 << 2);
            if (xa.x > THRESH0) { int q = atomicAdd(&s_cnt, 1); if (q < CAND) s_buf[q] = makekey(sortkey32(xa.x), ca + 0); }
            if (xa.y > THRESH0) { int q = atomicAdd(&s_cnt, 1); if (q < CAND) s_buf[q] = makekey(sortkey32(xa.y), ca + 1); }
            if (xa.z > THRESH0) { int q = atomicAdd(&s_cnt, 1); if (q < CAND) s_buf[q] = makekey(sortkey32(xa.z), ca + 2); }
            if (xa.w > THRESH0) { int q = atomicAdd(&s_cnt, 1); if (q < CAND) s_buf[q] = makekey(sortkey32(xa.w), ca + 3); }
            if (xb.x > THRESH0) { int q = atomicAdd(&s_cnt, 1); if (q < CAND) s_buf[q] = makekey(sortkey32(xb.x), cb + 0); }
            if (xb.y > THRESH0) { int q = atomicAdd(&s_cnt, 1); if (q < CAND) s_buf[q] = makekey(sortkey32(xb.y), cb + 1); }
            if (xb.z > THRESH0) { int q = atomicAdd(&s_cnt, 1); if (q < CAND) s_buf[q] = makekey(sortkey32(xb.z), cb + 2); }
            if (xb.w > THRESH0) { int q = atomicAdd(&s_cnt, 1); if (q < CAND) s_buf[q] = makekey(sortkey32(xb.w), cb + 3); }
        }

        const float ym = fmaxf(fmaxf(fmaxf(ya.x, ya.y), fmaxf(ya.z, ya.w)),
                               fmaxf(fmaxf(yb.x, yb.y), fmaxf(yb.z, yb.w)));
        if (ym != 0.0f) {
            const int ca = p + (v0 << 2);
            const int cb = p + (v1 << 2);
            if (ya.x != 0.0f) { int j = tbl_idx(xa.x); sum0 += s_tbl[j + TBL] - s_tbl[j]; flags |= g_catbit[ca + 0]; }
            if (ya.y != 0.0f) { int j = tbl_idx(xa.y); sum0 += s_tbl[j + TBL] - s_tbl[j]; flags |= g_catbit[ca + 1]; }
            if (ya.z != 0.0f) { int j = tbl_idx(xa.z); sum0 += s_tbl[j + TBL] - s_tbl[j]; flags |= g_catbit[ca + 2]; }
            if (ya.w != 0.0f) { int j = tbl_idx(xa.w); sum0 += s_tbl[j + TBL] - s_tbl[j]; flags |= g_catbit[ca + 3]; }
            if (yb.x != 0.0f) { int j = tbl_idx(xb.x); sum1 += s_tbl[j + TBL] - s_tbl[j]; flags |= g_catbit[cb + 0]; }
            if (yb.y != 0.0f) { int j = tbl_idx(xb.y); sum1 += s_tbl[j + TBL] - s_tbl[j]; flags |= g_catbit[cb + 1]; }
            if (yb.z != 0.0f) { int j = tbl_idx(xb.z); sum1 += s_tbl[j + TBL] - s_tbl[j]; flags |= g_catbit[cb + 2]; }
            if (yb.w != 0.0f) { int j = tbl_idx(xb.w); sum1 += s_tbl[j + TBL] - s_tbl[j]; flags |= g_catbit[cb + 3]; }
        }
    }

    // ---- remainder: single-quad (proven R7 body) ----
    for (int v = nv2 + tid; v < nv; v += 256) {
        const float4 xq = x4[v];
        const float4 yq = y4[v];

        sum0 += s_tbl[tbl_idx(xq.x)];
        sum0 += s_tbl[tbl_idx(xq.y)];
        sum0 += s_tbl[tbl_idx(xq.z)];
        sum0 += s_tbl[tbl_idx(xq.w)];

        const float xm = fmaxf(fmaxf(xq.x, xq.y), fmaxf(xq.z, xq.w));
        if (xm > THRESH0) {
            const int c0 = p + (v << 2);
            if (xq.x > THRESH0) { int q = atomicAdd(&s_cnt, 1); if (q < CAND) s_buf[q] = makekey(sortkey32(xq.x), c0 + 0); }
            if (xq.y > THRESH0) { int q = atomicAdd(&s_cnt, 1); if (q < CAND) s_buf[q] = makekey(sortkey32(xq.y), c0 + 1); }
            if (xq.z > THRESH0) { int q = atomicAdd(&s_cnt, 1); if (q < CAND) s_buf[q] = makekey(sortkey32(xq.z), c0 + 2); }
            if (xq.w > THRESH0) { int q = atomicAdd(&s_cnt, 1); if (q < CAND) s_buf[q] = makekey(sortkey32(xq.w), c0 + 3); }
        }
        const float ym = fmaxf(fmaxf(yq.x, yq.y), fmaxf(yq.z, yq.w));
        if (ym != 0.0f) {
            const int c0 = p + (v << 2);
            if (yq.x != 0.0f) { int j = tbl_idx(xq.x); sum0 += s_tbl[j + TBL] - s_tbl[j]; flags |= g_catbit[c0 + 0]; }
            if (yq.y != 0.0f) { int j = tbl_idx(xq.y); sum0 += s_tbl[j + TBL] - s_tbl[j]; flags |= g_catbit[c0 + 1]; }
            if (yq.z != 0.0f) { int j = tbl_idx(xq.z); sum0 += s_tbl[j + TBL] - s_tbl[j]; flags |= g_catbit[c0 + 2]; }
            if (yq.w != 0.0f) { int j = tbl_idx(xq.w); sum0 += s_tbl[j + TBL] - s_tbl[j]; flags |= g_catbit[c0 + 3]; }
        }
    }

    // ---- reduce sum & flags ----
    float sum = sum0 + sum1;
#pragma unroll
    for (int off = 16; off; off >>= 1) {
        sum   += __shfl_down_sync(FULLM, sum, off);
        flags |= __shfl_down_sync(FULLM, flags, off);
    }
    if (lane == 0) { s_sumw[warp] = sum; atomicOr(&s_flags, flags); }
    __syncthreads();

    // ---- resolve exact top-10 (fast path: 10 <= n <= CAND on first try) ----
    float thF = THRESH0;
    unsigned long long thK = 0ULL;
    bool useKey = false;
    int iter = 0;
    for (;;) {
        const int n = s_cnt;
        const bool done = (n >= 10 && n <= CAND) || iter >= 32;
        if (done || n > CAND) {
            if (warp == 0) {
                const int m = min(n, CAND);
                for (int kk = 0; kk < 10; ++kk) {
                    unsigned long long v = 0ULL;
                    for (int i = lane; i < m; i += 32) {
                        unsigned long long b = s_buf[i];
                        if (b > v) v = b;
                    }
#pragma unroll
                    for (int off = 16; off; off >>= 1) {
                        unsigned long long o = __shfl_down_sync(FULLM, v, off);
                        if (o > v) v = o;
                    }
                    unsigned long long w = __shfl_sync(FULLM, v, 0);
                    if (lane == 0) s_top[kk] = w;
                    for (int i = lane; i < m; i += 32)
                        if (s_buf[i] == w) s_buf[i] = 0ULL;
                }
            }
            __syncthreads();
            if (done) break;
            thK = s_top[9];
            useKey = true;        // recollect with key >= thK (>=10 guaranteed)
        } else {
            thF -= 4.0f;          // too few: lower the float threshold
            useKey = false;
        }
        __syncthreads();
        if (tid == 0) s_cnt = 0;
        __syncthreads();
        for (int c = tid; c < C; c += 256) {
            const float xv = xr[c];
            if (useKey) {
                unsigned long long key = makekey(sortkey32(xv), c);
                if (key >= thK) {
                    int q = atomicAdd(&s_cnt, 1);
                    if (q < CAND) s_buf[q] = key;
                }
            } else if (xv > thF) {
                int q = atomicAdd(&s_cnt, 1);
                if (q < CAND) s_buf[q] = makekey(sortkey32(xv), c);
            }
        }
        __syncthreads();
        ++iter;
    }

    // ---- correction for the top-10 elements (exact math) ----
    const int fl = s_flags;
    const bool p1 = (fl & 1) != 0, p2 = (fl & 2) != 0, p3 = (fl & 4) != 0;
    const bool has4 = !(p1 | p2 | p3);

    float delta = 0.0f;
    if (tid < 10 && s_top[tid] != 0ULL) {
        const unsigned idx = 0xFFFFFFFFu - (unsigned)(s_top[tid] & 0xFFFFFFFFull);
        const float xv = xr[idx];
        const float yv = yr[idx];
        const float sp = __fdividef(1.0f, 1.0f + __expf(-xv));
        const float sn = fminf(1.05f - sp, 1.0f);
        const bool  pos = (yv != 0.0f);
        const float pv  = pos ? sp : sn;
        const float l   = __logf(fmaxf(pv, 1e-8f));
        const float om  = 1.0f - pv;
        const float om2 = om * om;
        const float w   = pos ? om : om2 * om2;

        const int  cv  = cat[idx];
        const bool inm = inmap[idx] != 0;
        const bool condA = (!inm) && has4;
        const bool condB = (cv == 1 && p1) || (cv == 2 && p2) ||
                           (cv == 3 && p3) || (cv == 4 && has4);
        if (condA || condB) {
            const float factor = (pos ? sn : sp) * 2.0f;   // ALPHA3 = 2
            delta = l * w * (factor - 1.0f);
        }
    }
    if (warp == 0) {
#pragma unroll
        for (int off = 16; off; off >>= 1)
            delta += __shfl_down_sync(FULLM, delta, off);
    }
    if (tid == 0) {
        float tot = delta;
#pragma unroll
        for (int i = 0; i < 8; ++i) tot += s_sumw[i];
        g_rowsum[row] = tot;
    }

    // ---- last-block finalize: deterministic double reduction ----
    __threadfence();
    if (tid == 0) s_last = (atomicAdd(&g_count, 1) == gridDim.x - 1) ? 1 : 0;
    __syncthreads();
    if (s_last) {
        __threadfence();
        double* sd = (double*)s_buf;
        double acc = 0.0;
        for (int i = tid; i < B; i += 256) acc += (double)g_rowsum[i];
        sd[tid] = acc;
        __syncthreads();
#pragma unroll
        for (int off = 128; off; off >>= 1) {
            if (tid < off) sd[tid] += sd[tid + off];
            __syncthreads();
        }
        if (tid == 0) { out[0] = -(float)sd[0]; g_count = 0; }
    }
}

extern "C" void kernel_launch(void* const* d_in, const int* in_sizes, int n_in,
                              void* d_out, int out_size)
{
    const float*         X   = (const float*)d_in[0];
    const float*         Y   = (const float*)d_in[1];
    const int*           cat = (const int*)d_in[2];
    const unsigned char* inm = (const unsigned char*)d_in[3];

    const int C = in_sizes[2];        // per-class arrays -> 9605
    const int B = in_sizes[0] / C;    // 2048

    asl_build<<<(2 * TBL + C + 255) / 256, 256>>>(cat, C);
    asl_row_kernel<<<B, 256>>>(X, Y, cat, inm, C, B, (float*)d_out);
}

// round 11
// speedup vs baseline: 1.0775x; 1.0204x over previous
#include <cuda_runtime.h>
#include <cstdint>

#define CAND   256          // candidate buffer entries (u64)
#define TBL    1024         // bins per table
#define XSCALE 51.2f        // TBL / 20  (range [-10, 10])
#define XOFF   512.0f       // 10 * XSCALE
#define THRESH0 2.7f        // prefilter threshold (fallback makes any value correct)
#define FULLM  0xFFFFFFFFu
#define NSTG   3            // pipeline stages
#define PDIST  2            // prefetch distance (PDIST < NSTG)

static __device__ float g_rowsum[8192];
static __device__ float g_table[2 * TBL];          // [0..TBL)=f_neg, [TBL..2TBL)=f_pos
static __device__ unsigned char g_catbit[16384];   // (1<<(cat-1))&7
static __device__ int   g_count = 0;

// ---------------------------------------------------------------------------
__device__ __forceinline__ unsigned sortkey32(float x) {
    unsigned u = __float_as_uint(x);
    return u ^ ((unsigned)(((int)u) >> 31) | 0x80000000u);
}
__device__ __forceinline__ unsigned long long makekey(unsigned k32, int c) {
    return ((unsigned long long)k32 << 32) |
           (unsigned long long)(0xFFFFFFFFu - (unsigned)c);
}
__device__ __forceinline__ int tbl_idx(float xv) {
    float fx = fmaf(xv, XSCALE, XOFF);
    fx = fminf(fx, (float)(TBL - 1));
    fx = fmaxf(fx, 0.0f);
    return (int)fx;
}
__device__ __forceinline__ void cp16(void* dst_smem, const void* src_gmem) {
    unsigned d = (unsigned)__cvta_generic_to_shared(dst_smem);
    asm volatile("cp.async.cg.shared.global [%0], [%1], 16;"
                 :: "r"(d), "l"(src_gmem) : "memory");
}
__device__ __forceinline__ void cp_commit() {
    asm volatile("cp.async.commit_group;" ::: "memory");
}
template <int N>
__device__ __forceinline__ void cp_wait() {
    asm volatile("cp.async.wait_group %0;" :: "n"(N) : "memory");
}

// ---------------------------------------------------------------------------
// Kernel 0: build loss tables (exact math) + catbit LUT.
// ---------------------------------------------------------------------------
__global__ void asl_build(const int* __restrict__ cat, int C)
{
    int j = blockIdx.x * 256 + threadIdx.x;
    if (j < 2 * TBL) {
        bool pos = j >= TBL;
        int  q   = pos ? j - TBL : j;
        float x  = (q + 0.5f) * (20.0f / TBL) - 10.0f;
        float sp = 1.0f / (1.0f + expf(-x));
        float v;
        if (pos) {
            v = logf(fmaxf(sp, 1e-8f)) * (1.0f - sp);
        } else {
            float pv = fminf(1.05f - sp, 1.0f);
            float om = 1.0f - pv;
            float om2 = om * om;
            v = logf(fmaxf(pv, 1e-8f)) * om2 * om2;
        }
        g_table[j] = v;
    }
    int c = j - 2 * TBL;
    if (c >= 0 && c < C)
        g_catbit[c] = (unsigned char)((1 << (cat[c] - 1)) & 7);
}

// ---------------------------------------------------------------------------
// Kernel 1: persistent blocks; per-thread cp.async pipeline; one row at a time.
// ---------------------------------------------------------------------------
__global__ void __launch_bounds__(256, 6)
asl_row_kernel(const float* __restrict__ X,
               const float* __restrict__ Y,
               const int*   __restrict__ cat,
               const unsigned char* __restrict__ inmap,
               int C, int B, float* __restrict__ out)
{
    const int tid  = threadIdx.x;
    const int lane = tid & 31;
    const int warp = tid >> 5;

    __shared__ float  s_tbl[2 * TBL];                 // 8 KB
    __shared__ __align__(16) float4 s_px[NSTG][256];  // 12 KB
    __shared__ __align__(16) float4 s_py[NSTG][256];  // 12 KB
    __shared__ unsigned long long s_buf[CAND];        // 2 KB
    __shared__ unsigned long long s_top[10];
    __shared__ float s_sumw[8];
    __shared__ int s_flags, s_cnt, s_last;

    {   // table L2 -> smem (once per block)
        const float4* gt = (const float4*)g_table;
        float4* st = (float4*)s_tbl;
#pragma unroll
        for (int i = tid; i < (2 * TBL) / 4; i += 256) st[i] = gt[i];
    }
    __syncthreads();

    for (int row = blockIdx.x; row < B; row += gridDim.x) {
        if (tid == 0) { s_flags = 0; s_cnt = 0; }
        __syncthreads();

        const size_t base = (size_t)row * (size_t)C;
        const float* __restrict__ xr = X + base;
        const float* __restrict__ yr = Y + base;

        float sum = 0.0f;
        int flags = 0;

        // alignment: first element index whose address is 16B aligned
        const int p  = (int)((4 - (base & 3)) & 3);
        const int nv = (C - p) >> 2;
        const int t0 = p + (nv << 2);

        // prologue + tail (<=3 elements each)
        for (int c = tid; c < p; c += 256) {
            const float xv = xr[c], yv = yr[c];
            const int j = tbl_idx(xv);
            sum += s_tbl[j];
            if (yv != 0.0f) { sum += s_tbl[j + TBL] - s_tbl[j]; flags |= g_catbit[c]; }
            if (xv > THRESH0) {
                int q = atomicAdd(&s_cnt, 1);
                if (q < CAND) s_buf[q] = makekey(sortkey32(xv), c);
            }
        }
        for (int c = t0 + tid; c < C; c += 256) {
            const float xv = xr[c], yv = yr[c];
            const int j = tbl_idx(xv);
            sum += s_tbl[j];
            if (yv != 0.0f) { sum += s_tbl[j + TBL] - s_tbl[j]; flags |= g_catbit[c]; }
            if (xv > THRESH0) {
                int q = atomicAdd(&s_cnt, 1);
                if (q < CAND) s_buf[q] = makekey(sortkey32(xv), c);
            }
        }

        // ---- per-thread cp.async pipeline over this thread's quads ----
        const float4* __restrict__ x4 = (const float4*)(xr + p);
        const float4* __restrict__ y4 = (const float4*)(yr + p);
        const int ni = (nv > tid) ? ((nv - tid + 255) >> 8) : 0;

        // prologue: issue groups for iterations 0..PDIST-1
#pragma unroll
        for (int s = 0; s < PDIST; ++s) {
            if (s < ni) {
                const int v = tid + (s << 8);
                cp16(&s_px[s][tid], x4 + v);
                cp16(&s_py[s][tid], y4 + v);
            }
            cp_commit();
        }

        for (int i = 0; i < ni; ++i) {
            cp_wait<PDIST - 1>();                     // group #i complete
            const int stage = i % NSTG;
            const float4 xq = s_px[stage][tid];
            const float4 yq = s_py[stage][tid];
            const int v  = tid + (i << 8);
            const int c0 = p + (v << 2);

            // unconditional neg-table sums
            sum += s_tbl[tbl_idx(xq.x)];
            sum += s_tbl[tbl_idx(xq.y)];
            sum += s_tbl[tbl_idx(xq.z)];
            sum += s_tbl[tbl_idx(xq.w)];

            const float xm = fmaxf(fmaxf(xq.x, xq.y), fmaxf(xq.z, xq.w));
            if (xm > THRESH0) {
                if (xq.x > THRESH0) { int q = atomicAdd(&s_cnt, 1); if (q < CAND) s_buf[q] = makekey(sortkey32(xq.x), c0 + 0); }
                if (xq.y > THRESH0) { int q = atomicAdd(&s_cnt, 1); if (q < CAND) s_buf[q] = makekey(sortkey32(xq.y), c0 + 1); }
                if (xq.z > THRESH0) { int q = atomicAdd(&s_cnt, 1); if (q < CAND) s_buf[q] = makekey(sortkey32(xq.z), c0 + 2); }
                if (xq.w > THRESH0) { int q = atomicAdd(&s_cnt, 1); if (q < CAND) s_buf[q] = makekey(sortkey32(xq.w), c0 + 3); }
            }
            const float ym = fmaxf(fmaxf(yq.x, yq.y), fmaxf(yq.z, yq.w));
            if (ym != 0.0f) {
                if (yq.x != 0.0f) { int j = tbl_idx(xq.x); sum += s_tbl[j + TBL] - s_tbl[j]; flags |= g_catbit[c0 + 0]; }
                if (yq.y != 0.0f) { int j = tbl_idx(xq.y); sum += s_tbl[j + TBL] - s_tbl[j]; flags |= g_catbit[c0 + 1]; }
                if (yq.z != 0.0f) { int j = tbl_idx(xq.z); sum += s_tbl[j + TBL] - s_tbl[j]; flags |= g_catbit[c0 + 2]; }
                if (yq.w != 0.0f) { int j = tbl_idx(xq.w); sum += s_tbl[j + TBL] - s_tbl[j]; flags |= g_catbit[c0 + 3]; }
            }

            // issue loads for iteration i+PDIST into stage (i+PDIST)%NSTG
            const int ip = i + PDIST;
            if (ip < ni) {
                const int vp = tid + (ip << 8);
                const int sp2 = ip % NSTG;
                cp16(&s_px[sp2][tid], x4 + vp);
                cp16(&s_py[sp2][tid], y4 + vp);
            }
            cp_commit();
        }
        cp_wait<0>();                                 // drain before smem reuse

        // ---- reduce sum & flags ----
#pragma unroll
        for (int off = 16; off; off >>= 1) {
            sum   += __shfl_down_sync(FULLM, sum, off);
            flags |= __shfl_down_sync(FULLM, flags, off);
        }
        if (lane == 0) { s_sumw[warp] = sum; atomicOr(&s_flags, flags); }
        __syncthreads();

        // ---- resolve exact top-10 (fast path: 10 <= n <= CAND first try) ----
        float thF = THRESH0;
        unsigned long long thK = 0ULL;
        bool useKey = false;
        int iter = 0;
        for (;;) {
            const int n = s_cnt;
            const bool done = (n >= 10 && n <= CAND) || iter >= 32;
            if (done || n > CAND) {
                if (warp == 0) {
                    const int m = min(n, CAND);
                    for (int kk = 0; kk < 10; ++kk) {
                        unsigned long long v = 0ULL;
                        for (int i = lane; i < m; i += 32) {
                            unsigned long long b = s_buf[i];
                            if (b > v) v = b;
                        }
#pragma unroll
                        for (int off = 16; off; off >>= 1) {
                            unsigned long long o = __shfl_down_sync(FULLM, v, off);
                            if (o > v) v = o;
                        }
                        unsigned long long w = __shfl_sync(FULLM, v, 0);
                        if (lane == 0) s_top[kk] = w;
                        for (int i = lane; i < m; i += 32)
                            if (s_buf[i] == w) s_buf[i] = 0ULL;
                    }
                }
                __syncthreads();
                if (done) break;
                thK = s_top[9];
                useKey = true;        // recollect with key >= thK (>=10 guaranteed)
            } else {
                thF -= 4.0f;          // too few: lower the float threshold
                useKey = false;
            }
            __syncthreads();
            if (tid == 0) s_cnt = 0;
            __syncthreads();
            for (int c = tid; c < C; c += 256) {
                const float xv = xr[c];
                if (useKey) {
                    unsigned long long key = makekey(sortkey32(xv), c);
                    if (key >= thK) {
                        int q = atomicAdd(&s_cnt, 1);
                        if (q < CAND) s_buf[q] = key;
                    }
                } else if (xv > thF) {
                    int q = atomicAdd(&s_cnt, 1);
                    if (q < CAND) s_buf[q] = makekey(sortkey32(xv), c);
                }
            }
            __syncthreads();
            ++iter;
        }

        // ---- correction for the top-10 elements (exact math) ----
        const int fl = s_flags;
        const bool p1 = (fl & 1) != 0, p2 = (fl & 2) != 0, p3 = (fl & 4) != 0;
        const bool has4 = !(p1 | p2 | p3);

        float delta = 0.0f;
        if (tid < 10 && s_top[tid] != 0ULL) {
            const unsigned idx = 0xFFFFFFFFu - (unsigned)(s_top[tid] & 0xFFFFFFFFull);
            const float xv = xr[idx];
            const float yv = yr[idx];
            const float sp = __fdividef(1.0f, 1.0f + __expf(-xv));
            const float sn = fminf(1.05f - sp, 1.0f);
            const bool  pos = (yv != 0.0f);
            const float pv  = pos ? sp : sn;
            const float l   = __logf(fmaxf(pv, 1e-8f));
            const float om  = 1.0f - pv;
            const float om2 = om * om;
            const float w   = pos ? om : om2 * om2;

            const int  cv  = cat[idx];
            const bool inm = inmap[idx] != 0;
            const bool condA = (!inm) && has4;
            const bool condB = (cv == 1 && p1) || (cv == 2 && p2) ||
                               (cv == 3 && p3) || (cv == 4 && has4);
            if (condA || condB) {
                const float factor = (pos ? sn : sp) * 2.0f;   // ALPHA3 = 2
                delta = l * w * (factor - 1.0f);
            }
        }
        if (warp == 0) {
#pragma unroll
            for (int off = 16; off; off >>= 1)
                delta += __shfl_down_sync(FULLM, delta, off);
        }
        if (tid == 0) {
            float tot = delta;
#pragma unroll
            for (int i = 0; i < 8; ++i) tot += s_sumw[i];
            g_rowsum[row] = tot;
        }
        __syncthreads();   // protect s_buf/s_cnt before next row resets
    }

    // ---- last-block finalize: deterministic double reduction ----
    __threadfence();
    if (tid == 0) s_last = (atomicAdd(&g_count, 1) == gridDim.x - 1) ? 1 : 0;
    __syncthreads();
    if (s_last) {
        __threadfence();
        double* sd = (double*)s_px;     // reuse pipeline smem as scratch
        double acc = 0.0;
        for (int i = tid; i < B; i += 256) acc += (double)g_rowsum[i];
        sd[tid] = acc;
        __syncthreads();
#pragma unroll
        for (int off = 128; off; off >>= 1) {
            if (tid < off) sd[tid] += sd[tid + off];
            __syncthreads();
        }
        if (tid == 0) { out[0] = -(float)sd[0]; g_count = 0; }
    }
}

extern "C" void kernel_launch(void* const* d_in, const int* in_sizes, int n_in,
                              void* d_out, int out_size)
{
    const float*         X   = (const float*)d_in[0];
    const float*         Y   = (const float*)d_in[1];
    const int*           cat = (const int*)d_in[2];
    const unsigned char* inm = (const unsigned char*)d_in[3];

    const int C = in_sizes[2];        // per-class arrays -> 9605
    const int B = in_sizes[0] / C;    // 2048

    int nsm = 148, bpsm = 6;
    cudaDeviceGetAttribute(&nsm, cudaDevAttrMultiProcessorCount, 0);
    cudaOccupancyMaxActiveBlocksPerMultiprocessor(&bpsm, asl_row_kernel, 256, 0);
    if (bpsm < 1) bpsm = 1;
    int grid = nsm * bpsm;
    if (grid > B) grid = B;

    asl_build<<<(2 * TBL + C + 255) / 256, 256>>>(cat, C);
    asl_row_kernel<<<grid, 256>>>(X, Y, cat, inm, C, B, (float*)d_out);
}

// round 12
// speedup vs baseline: 1.2181x; 1.1304x over previous
#include <cuda_runtime.h>
#include <cstdint>

#define CAND 512           // candidate buffer entries (u64)
#define TBL  1024          // bins per table
#define XSCALE 51.2f       // TBL / 20  (range [-10, 10])
#define XOFF   512.0f      // 10 * XSCALE
#define THRESH0 2.7f       // prefilter threshold (fallback makes any value correct)
#define FULLM 0xFFFFFFFFu

static __device__ float g_rowsum[8192];
static __device__ float g_table[2 * TBL];          // [0..TBL)=f_neg, [TBL..2TBL)=f_pos
static __device__ unsigned char g_catbit[16384];   // (1<<(cat-1))&7
static __device__ int   g_count = 0;

// ---------------------------------------------------------------------------
__device__ __forceinline__ unsigned sortkey32(float x) {
    unsigned u = __float_as_uint(x);
    return u ^ ((unsigned)(((int)u) >> 31) | 0x80000000u);
}
__device__ __forceinline__ unsigned long long makekey(unsigned k32, int c) {
    return ((unsigned long long)k32 << 32) |
           (unsigned long long)(0xFFFFFFFFu - (unsigned)c);
}
// saturating index: negatives clamp to 0 in the F2I itself (cvt.rzi.u32 sat)
__device__ __forceinline__ int tbl_idx(float xv) {
    unsigned j = __float2uint_rz(fmaf(xv, XSCALE, XOFF));
    return (int)umin(j, (unsigned)(TBL - 1));
}

// ---------------------------------------------------------------------------
// Kernel 0: build loss tables (exact math) + catbit LUT.
// ---------------------------------------------------------------------------
__global__ void asl_build(const int* __restrict__ cat, int C)
{
    int j = blockIdx.x * 256 + threadIdx.x;
    if (j < 2 * TBL) {
        bool pos = j >= TBL;
        int  q   = pos ? j - TBL : j;
        float x  = (q + 0.5f) * (20.0f / TBL) - 10.0f;
        float sp = 1.0f / (1.0f + expf(-x));
        float v;
        if (pos) {
            v = logf(fmaxf(sp, 1e-8f)) * (1.0f - sp);
        } else {
            float pv = fminf(1.05f - sp, 1.0f);
            float om = 1.0f - pv;
            float om2 = om * om;
            v = logf(fmaxf(pv, 1e-8f)) * om2 * om2;
        }
        g_table[j] = v;
    }
    int c = j - 2 * TBL;
    if (c >= 0 && c < C)
        g_catbit[c] = (unsigned char)((1 << (cat[c] - 1)) & 7);
}

// ---------------------------------------------------------------------------
// Kernel 1: one block per row.
// ---------------------------------------------------------------------------
__global__ void __launch_bounds__(256, 8)
asl_row_kernel(const float* __restrict__ X,
               const float* __restrict__ Y,
               const int*   __restrict__ cat,
               const unsigned char* __restrict__ inmap,
               int C, int B, float* __restrict__ out)
{
    const int row  = blockIdx.x;
    const int tid  = threadIdx.x;
    const int lane = tid & 31;
    const int warp = tid >> 5;

    const float* __restrict__ xr = X + (size_t)row * C;
    const float* __restrict__ yr = Y + (size_t)row * C;

    __shared__ float s_tbl[2 * TBL];              // 8 KB
    __shared__ unsigned long long s_buf[CAND];    // 4 KB
    __shared__ unsigned long long s_top[10];
    __shared__ float s_sumw[8];
    __shared__ int s_flags, s_cnt, s_last;

    {   // table L2 -> smem
        const float4* gt = (const float4*)g_table;
        float4* st = (float4*)s_tbl;
#pragma unroll
        for (int i = tid; i < (2 * TBL) / 4; i += 256) st[i] = gt[i];
    }
    if (tid == 0) { s_flags = 0; s_cnt = 0; }
    __syncthreads();

    float sum0 = 0.0f, sum1 = 0.0f;
    int flags = 0;

    // alignment: first element index whose address is 16B aligned
    const int p = (int)((4 - (((size_t)row * (size_t)C) & 3)) & 3);
    const int nv = (C - p) >> 2;
    const int t0 = p + (nv << 2);

    // prologue + tail (<=3 elements each)
    for (int c = tid; c < p; c += 256) {
        const float xv = xr[c], yv = yr[c];
        const int j = tbl_idx(xv);
        sum0 += s_tbl[j];
        if (yv != 0.0f) { sum0 += s_tbl[j + TBL] - s_tbl[j]; flags |= g_catbit[c]; }
        if (xv > THRESH0) {
            int q = atomicAdd(&s_cnt, 1);
            if (q < CAND) s_buf[q] = makekey(sortkey32(xv), c);
        }
    }
    for (int c = t0 + tid; c < C; c += 256) {
        const float xv = xr[c], yv = yr[c];
        const int j = tbl_idx(xv);
        sum0 += s_tbl[j];
        if (yv != 0.0f) { sum0 += s_tbl[j + TBL] - s_tbl[j]; flags |= g_catbit[c]; }
        if (xv > THRESH0) {
            int q = atomicAdd(&s_cnt, 1);
            if (q < CAND) s_buf[q] = makekey(sortkey32(xv), c);
        }
    }

    // ---- main vectorized streaming loop (single quad, max occupancy) ----
    const float4* __restrict__ x4 = (const float4*)(xr + p);
    const float4* __restrict__ y4 = (const float4*)(yr + p);

    for (int v = tid; v < nv; v += 256) {
        const float4 xq = __ldcs(x4 + v);
        const float4 yq = __ldcs(y4 + v);

        const int j0 = tbl_idx(xq.x);
        const int j1 = tbl_idx(xq.y);
        const int j2 = tbl_idx(xq.z);
        const int j3 = tbl_idx(xq.w);
        sum0 += s_tbl[j0];
        sum1 += s_tbl[j1];
        sum0 += s_tbl[j2];
        sum1 += s_tbl[j3];

        // rare-path gates: any x above threshold OR any y nonzero (y in {0,1})
        const float xm = fmaxf(fmaxf(xq.x, xq.y), fmaxf(xq.z, xq.w));
        const unsigned yb = __float_as_uint(yq.x) | __float_as_uint(yq.y) |
                            __float_as_uint(yq.z) | __float_as_uint(yq.w);
        if ((xm > THRESH0) || (yb != 0u)) {
            const int c0 = p + (v << 2);
            if (xm > THRESH0) {
                if (xq.x > THRESH0) { int q = atomicAdd(&s_cnt, 1); if (q < CAND) s_buf[q] = makekey(sortkey32(xq.x), c0 + 0); }
                if (xq.y > THRESH0) { int q = atomicAdd(&s_cnt, 1); if (q < CAND) s_buf[q] = makekey(sortkey32(xq.y), c0 + 1); }
                if (xq.z > THRESH0) { int q = atomicAdd(&s_cnt, 1); if (q < CAND) s_buf[q] = makekey(sortkey32(xq.z), c0 + 2); }
                if (xq.w > THRESH0) { int q = atomicAdd(&s_cnt, 1); if (q < CAND) s_buf[q] = makekey(sortkey32(xq.w), c0 + 3); }
            }
            if (yb != 0u) {
                if (yq.x != 0.0f) { sum0 += s_tbl[j0 + TBL] - s_tbl[j0]; flags |= g_catbit[c0 + 0]; }
                if (yq.y != 0.0f) { sum1 += s_tbl[j1 + TBL] - s_tbl[j1]; flags |= g_catbit[c0 + 1]; }
                if (yq.z != 0.0f) { sum0 += s_tbl[j2 + TBL] - s_tbl[j2]; flags |= g_catbit[c0 + 2]; }
                if (yq.w != 0.0f) { sum1 += s_tbl[j3 + TBL] - s_tbl[j3]; flags |= g_catbit[c0 + 3]; }
            }
        }
    }

    // ---- reduce sum & flags ----
    float sum = sum0 + sum1;
#pragma unroll
    for (int off = 16; off; off >>= 1) {
        sum   += __shfl_down_sync(FULLM, sum, off);
        flags |= __shfl_down_sync(FULLM, flags, off);
    }
    if (lane == 0) { s_sumw[warp] = sum; atomicOr(&s_flags, flags); }
    __syncthreads();

    // ---- resolve exact top-10 (fast path: 10 <= n <= CAND on first try) ----
    float thF = THRESH0;
    unsigned long long thK = 0ULL;
    bool useKey = false;
    int iter = 0;
    for (;;) {
        const int n = s_cnt;
        const bool done = (n >= 10 && n <= CAND) || iter >= 32;
        if (done || n > CAND) {
            if (warp == 0) {
                const int m = min(n, CAND);
                for (int kk = 0; kk < 10; ++kk) {
                    unsigned long long v = 0ULL;
                    for (int i = lane; i < m; i += 32) {
                        unsigned long long b = s_buf[i];
                        if (b > v) v = b;
                    }
#pragma unroll
                    for (int off = 16; off; off >>= 1) {
                        unsigned long long o = __shfl_down_sync(FULLM, v, off);
                        if (o > v) v = o;
                    }
                    unsigned long long w = __shfl_sync(FULLM, v, 0);
                    if (lane == 0) s_top[kk] = w;
                    for (int i = lane; i < m; i += 32)
                        if (s_buf[i] == w) s_buf[i] = 0ULL;
                }
            }
            __syncthreads();
            if (done) break;
            thK = s_top[9];
            useKey = true;        // recollect with key >= thK (>=10 guaranteed)
        } else {
            thF -= 4.0f;          // too few: lower the float threshold
            useKey = false;
        }
        __syncthreads();
        if (tid == 0) s_cnt = 0;
        __syncthreads();
        for (int c = tid; c < C; c += 256) {
            const float xv = xr[c];
            if (useKey) {
                unsigned long long key = makekey(sortkey32(xv), c);
                if (key >= thK) {
                    int q = atomicAdd(&s_cnt, 1);
                    if (q < CAND) s_buf[q] = key;
                }
            } else if (xv > thF) {
                int q = atomicAdd(&s_cnt, 1);
                if (q < CAND) s_buf[q] = makekey(sortkey32(xv), c);
            }
        }
        __syncthreads();
        ++iter;
    }

    // ---- correction for the top-10 elements (exact math) ----
    const int fl = s_flags;
    const bool p1 = (fl & 1) != 0, p2 = (fl & 2) != 0, p3 = (fl & 4) != 0;
    const bool has4 = !(p1 | p2 | p3);

    float delta = 0.0f;
    if (tid < 10 && s_top[tid] != 0ULL) {
        const unsigned idx = 0xFFFFFFFFu - (unsigned)(s_top[tid] & 0xFFFFFFFFull);
        const float xv = xr[idx];
        const float yv = yr[idx];
        const float sp = __fdividef(1.0f, 1.0f + __expf(-xv));
        const float sn = fminf(1.05f - sp, 1.0f);
        const bool  pos = (yv != 0.0f);
        const float pv  = pos ? sp : sn;
        const float l   = __logf(fmaxf(pv, 1e-8f));
        const float om  = 1.0f - pv;
        const float om2 = om * om;
        const float w   = pos ? om : om2 * om2;

        const int  cv  = cat[idx];
        const bool inm = inmap[idx] != 0;
        const bool condA = (!inm) && has4;
        const bool condB = (cv == 1 && p1) || (cv == 2 && p2) ||
                           (cv == 3 && p3) || (cv == 4 && has4);
        if (condA || condB) {
            const float factor = (pos ? sn : sp) * 2.0f;   // ALPHA3 = 2
            delta = l * w * (factor - 1.0f);
        }
    }
    if (warp == 0) {
#pragma unroll
        for (int off = 16; off; off >>= 1)
            delta += __shfl_down_sync(FULLM, delta, off);
    }
    if (tid == 0) {
        float tot = delta;
#pragma unroll
        for (int i = 0; i < 8; ++i) tot += s_sumw[i];
        g_rowsum[row] = tot;
    }

    // ---- last-block finalize: deterministic double reduction ----
    __threadfence();
    if (tid == 0) s_last = (atomicAdd(&g_count, 1) == gridDim.x - 1) ? 1 : 0;
    __syncthreads();
    if (s_last) {
        __threadfence();
        double* sd = (double*)s_buf;
        double acc = 0.0;
        for (int i = tid; i < B; i += 256) acc += (double)g_rowsum[i];
        sd[tid] = acc;
        __syncthreads();
#pragma unroll
        for (int off = 128; off; off >>= 1) {
            if (tid < off) sd[tid] += sd[tid + off];
            __syncthreads();
        }
        if (tid == 0) { out[0] = -(float)sd[0]; g_count = 0; }
    }
}

extern "C" void kernel_launch(void* const* d_in, const int* in_sizes, int n_in,
                              void* d_out, int out_size)
{
    const float*         X   = (const float*)d_in[0];
    const float*         Y   = (const float*)d_in[1];
    const int*           cat = (const int*)d_in[2];
    const unsigned char* inm = (const unsigned char*)d_in[3];

    const int C = in_sizes[2];        // per-class arrays -> 9605
    const int B = in_sizes[0] / C;    // 2048

    asl_build<<<(2 * TBL + C + 255) / 256, 256>>>(cat, C);
    asl_row_kernel<<<B, 256>>>(X, Y, cat, inm, C, B, (float*)d_out);
}

// round 13
// speedup vs baseline: 1.2239x; 1.0048x over previous
#include <cuda_runtime.h>
#include <cstdint>

#define CAND 512           // candidate buffer entries (u64)
#define TBL  1024          // bins per table
#define XSCALE 51.2f       // TBL / 20  (range [-10, 10])
#define XOFF   512.0f      // 10 * XSCALE
#define THRESH0 2.7f       // prefilter threshold (fallback makes any value correct)
#define FULLM 0xFFFFFFFFu

static __device__ float g_rowsum[8192];
static __device__ float g_table[2 * TBL];          // [0..TBL)=f_neg, [TBL..2TBL)=f_pos
static __device__ unsigned char g_catbit[16384];   // (1<<(cat-1))&7
static __device__ int   g_count = 0;

// ---------------------------------------------------------------------------
__device__ __forceinline__ unsigned sortkey32(float x) {
    unsigned u = __float_as_uint(x);
    return u ^ ((unsigned)(((int)u) >> 31) | 0x80000000u);
}
__device__ __forceinline__ unsigned long long makekey(unsigned k32, int c) {
    return ((unsigned long long)k32 << 32) |
           (unsigned long long)(0xFFFFFFFFu - (unsigned)c);
}
// saturating index: negatives clamp to 0 in the F2I itself
__device__ __forceinline__ int tbl_idx(float xv) {
    unsigned j = __float2uint_rz(fmaf(xv, XSCALE, XOFF));
    return (int)umin(j, (unsigned)(TBL - 1));
}

// ---------------------------------------------------------------------------
// Kernel 0: build loss tables (exact math) + catbit LUT.
// ---------------------------------------------------------------------------
__global__ void asl_build(const int* __restrict__ cat, int C)
{
    int j = blockIdx.x * 256 + threadIdx.x;
    if (j < 2 * TBL) {
        bool pos = j >= TBL;
        int  q   = pos ? j - TBL : j;
        float x  = (q + 0.5f) * (20.0f / TBL) - 10.0f;
        float sp = 1.0f / (1.0f + expf(-x));
        float v;
        if (pos) {
            v = logf(fmaxf(sp, 1e-8f)) * (1.0f - sp);
        } else {
            float pv = fminf(1.05f - sp, 1.0f);
            float om = 1.0f - pv;
            float om2 = om * om;
            v = logf(fmaxf(pv, 1e-8f)) * om2 * om2;
        }
        g_table[j] = v;
    }
    int c = j - 2 * TBL;
    if (c >= 0 && c < C)
        g_catbit[c] = (unsigned char)((1 << (cat[c] - 1)) & 7);
}

// ---------------------------------------------------------------------------
// Kernel 1: 2 rows per block (single resident wave); proven R12 row body.
// ---------------------------------------------------------------------------
__global__ void __launch_bounds__(256, 8)
asl_row_kernel(const float* __restrict__ X,
               const float* __restrict__ Y,
               const int*   __restrict__ cat,
               const unsigned char* __restrict__ inmap,
               int C, int B, float* __restrict__ out)
{
    const int tid  = threadIdx.x;
    const int lane = tid & 31;
    const int warp = tid >> 5;

    __shared__ float s_tbl[2 * TBL];              // 8 KB
    __shared__ unsigned long long s_buf[CAND];    // 4 KB
    __shared__ unsigned long long s_top[10];
    __shared__ float s_sumw[8];
    __shared__ int s_flags, s_cnt, s_last;

    {   // table L2 -> smem (once per block, amortized over 2 rows)
        const float4* gt = (const float4*)g_table;
        float4* st = (float4*)s_tbl;
#pragma unroll
        for (int i = tid; i < (2 * TBL) / 4; i += 256) st[i] = gt[i];
    }
    __syncthreads();

    for (int row = blockIdx.x; row < B; row += gridDim.x) {
        if (tid == 0) { s_flags = 0; s_cnt = 0; }
        __syncthreads();

        const float* __restrict__ xr = X + (size_t)row * C;
        const float* __restrict__ yr = Y + (size_t)row * C;

        float sum0 = 0.0f, sum1 = 0.0f;
        int flags = 0;

        // alignment: first element index whose address is 16B aligned
        const int p = (int)((4 - (((size_t)row * (size_t)C) & 3)) & 3);
        const int nv = (C - p) >> 2;
        const int t0 = p + (nv << 2);

        // prologue + tail (<=3 elements each)
        for (int c = tid; c < p; c += 256) {
            const float xv = xr[c], yv = yr[c];
            const int j = tbl_idx(xv);
            sum0 += s_tbl[j];
            if (yv != 0.0f) { sum0 += s_tbl[j + TBL] - s_tbl[j]; flags |= g_catbit[c]; }
            if (xv > THRESH0) {
                int q = atomicAdd(&s_cnt, 1);
                if (q < CAND) s_buf[q] = makekey(sortkey32(xv), c);
            }
        }
        for (int c = t0 + tid; c < C; c += 256) {
            const float xv = xr[c], yv = yr[c];
            const int j = tbl_idx(xv);
            sum0 += s_tbl[j];
            if (yv != 0.0f) { sum0 += s_tbl[j + TBL] - s_tbl[j]; flags |= g_catbit[c]; }
            if (xv > THRESH0) {
                int q = atomicAdd(&s_cnt, 1);
                if (q < CAND) s_buf[q] = makekey(sortkey32(xv), c);
            }
        }

        // ---- main vectorized streaming loop (single quad, max occupancy) ----
        const float4* __restrict__ x4 = (const float4*)(xr + p);
        const float4* __restrict__ y4 = (const float4*)(yr + p);

        for (int v = tid; v < nv; v += 256) {
            const float4 xq = __ldcs(x4 + v);
            const float4 yq = __ldcs(y4 + v);

            const int j0 = tbl_idx(xq.x);
            const int j1 = tbl_idx(xq.y);
            const int j2 = tbl_idx(xq.z);
            const int j3 = tbl_idx(xq.w);
            sum0 += s_tbl[j0];
            sum1 += s_tbl[j1];
            sum0 += s_tbl[j2];
            sum1 += s_tbl[j3];

            // rare-path gates: any x above threshold OR any y nonzero (y in {0,1})
            const float xm = fmaxf(fmaxf(xq.x, xq.y), fmaxf(xq.z, xq.w));
            const unsigned yb = __float_as_uint(yq.x) | __float_as_uint(yq.y) |
                                __float_as_uint(yq.z) | __float_as_uint(yq.w);
            if ((xm > THRESH0) || (yb != 0u)) {
                const int c0 = p + (v << 2);
                if (xm > THRESH0) {
                    if (xq.x > THRESH0) { int q = atomicAdd(&s_cnt, 1); if (q < CAND) s_buf[q] = makekey(sortkey32(xq.x), c0 + 0); }
                    if (xq.y > THRESH0) { int q = atomicAdd(&s_cnt, 1); if (q < CAND) s_buf[q] = makekey(sortkey32(xq.y), c0 + 1); }
                    if (xq.z > THRESH0) { int q = atomicAdd(&s_cnt, 1); if (q < CAND) s_buf[q] = makekey(sortkey32(xq.z), c0 + 2); }
                    if (xq.w > THRESH0) { int q = atomicAdd(&s_cnt, 1); if (q < CAND) s_buf[q] = makekey(sortkey32(xq.w), c0 + 3); }
                }
                if (yb != 0u) {
                    if (yq.x != 0.0f) { sum0 += s_tbl[j0 + TBL] - s_tbl[j0]; flags |= g_catbit[c0 + 0]; }
                    if (yq.y != 0.0f) { sum1 += s_tbl[j1 + TBL] - s_tbl[j1]; flags |= g_catbit[c0 + 1]; }
                    if (yq.z != 0.0f) { sum0 += s_tbl[j2 + TBL] - s_tbl[j2]; flags |= g_catbit[c0 + 2]; }
                    if (yq.w != 0.0f) { sum1 += s_tbl[j3 + TBL] - s_tbl[j3]; flags |= g_catbit[c0 + 3]; }
                }
            }
        }

        // ---- reduce sum & flags ----
        float sum = sum0 + sum1;
#pragma unroll
        for (int off = 16; off; off >>= 1) {
            sum   += __shfl_down_sync(FULLM, sum, off);
            flags |= __shfl_down_sync(FULLM, flags, off);
        }
        if (lane == 0) { s_sumw[warp] = sum; atomicOr(&s_flags, flags); }
        __syncthreads();

        // ---- resolve exact top-10 (fast path: 10 <= n <= CAND first try) ----
        float thF = THRESH0;
        unsigned long long thK = 0ULL;
        bool useKey = false;
        int iter = 0;
        for (;;) {
            const int n = s_cnt;
            const bool done = (n >= 10 && n <= CAND) || iter >= 32;
            if (done || n > CAND) {
                if (warp == 0) {
                    const int m = min(n, CAND);
                    for (int kk = 0; kk < 10; ++kk) {
                        unsigned long long v = 0ULL;
                        for (int i = lane; i < m; i += 32) {
                            unsigned long long b = s_buf[i];
                            if (b > v) v = b;
                        }
#pragma unroll
                        for (int off = 16; off; off >>= 1) {
                            unsigned long long o = __shfl_down_sync(FULLM, v, off);
                            if (o > v) v = o;
                        }
                        unsigned long long w = __shfl_sync(FULLM, v, 0);
                        if (lane == 0) s_top[kk] = w;
                        for (int i = lane; i < m; i += 32)
                            if (s_buf[i] == w) s_buf[i] = 0ULL;
                    }
                }
                __syncthreads();
                if (done) break;
                thK = s_top[9];
                useKey = true;        // recollect with key >= thK (>=10 guaranteed)
            } else {
                thF -= 4.0f;          // too few: lower the float threshold
                useKey = false;
            }
            __syncthreads();
            if (tid == 0) s_cnt = 0;
            __syncthreads();
            for (int c = tid; c < C; c += 256) {
                const float xv = xr[c];
                if (useKey) {
                    unsigned long long key = makekey(sortkey32(xv), c);
                    if (key >= thK) {
                        int q = atomicAdd(&s_cnt, 1);
                        if (q < CAND) s_buf[q] = key;
                    }
                } else if (xv > thF) {
                    int q = atomicAdd(&s_cnt, 1);
                    if (q < CAND) s_buf[q] = makekey(sortkey32(xv), c);
                }
            }
            __syncthreads();
            ++iter;
        }

        // ---- correction for the top-10 elements (exact math) ----
        const int fl = s_flags;
        const bool p1 = (fl & 1) != 0, p2 = (fl & 2) != 0, p3 = (fl & 4) != 0;
        const bool has4 = !(p1 | p2 | p3);

        float delta = 0.0f;
        if (tid < 10 && s_top[tid] != 0ULL) {
            const unsigned idx = 0xFFFFFFFFu - (unsigned)(s_top[tid] & 0xFFFFFFFFull);
            const float xv = xr[idx];
            const float yv = yr[idx];
            const float sp = __fdividef(1.0f, 1.0f + __expf(-xv));
            const float sn = fminf(1.05f - sp, 1.0f);
            const bool  pos = (yv != 0.0f);
            const float pv  = pos ? sp : sn;
            const float l   = __logf(fmaxf(pv, 1e-8f));
            const float om  = 1.0f - pv;
            const float om2 = om * om;
            const float w   = pos ? om : om2 * om2;

            const int  cv  = cat[idx];
            const bool inm = inmap[idx] != 0;
            const bool condA = (!inm) && has4;
            const bool condB = (cv == 1 && p1) || (cv == 2 && p2) ||
                               (cv == 3 && p3) || (cv == 4 && has4);
            if (condA || condB) {
                const float factor = (pos ? sn : sp) * 2.0f;   // ALPHA3 = 2
                delta = l * w * (factor - 1.0f);
            }
        }
        if (warp == 0) {
#pragma unroll
            for (int off = 16; off; off >>= 1)
                delta += __shfl_down_sync(FULLM, delta, off);
        }
        if (tid == 0) {
            float tot = delta;
#pragma unroll
            for (int i = 0; i < 8; ++i) tot += s_sumw[i];
            g_rowsum[row] = tot;
        }
        __syncthreads();   // protect s_buf/s_cnt/s_top before next row resets
    }

    // ---- last-block finalize: deterministic double reduction ----
    __threadfence();
    if (tid == 0) s_last = (atomicAdd(&g_count, 1) == gridDim.x - 1) ? 1 : 0;
    __syncthreads();
    if (s_last) {
        __threadfence();
        double* sd = (double*)s_buf;
        double acc = 0.0;
        for (int i = tid; i < B; i += 256) acc += (double)g_rowsum[i];
        sd[tid] = acc;
        __syncthreads();
#pragma unroll
        for (int off = 128; off; off >>= 1) {
            if (tid < off) sd[tid] += sd[tid + off];
            __syncthreads();
        }
        if (tid == 0) { out[0] = -(float)sd[0]; g_count = 0; }
    }
}

extern "C" void kernel_launch(void* const* d_in, const int* in_sizes, int n_in,
                              void* d_out, int out_size)
{
    const float*         X   = (const float*)d_in[0];
    const float*         Y   = (const float*)d_in[1];
    const int*           cat = (const int*)d_in[2];
    const unsigned char* inm = (const unsigned char*)d_in[3];

    const int C = in_sizes[2];        // per-class arrays -> 9605
    const int B = in_sizes[0] / C;    // 2048

    // 2 rows per block: grid fits in ONE resident wave (148 SMs x 8 blocks)
    int grid = (B + 1) / 2;
    if (grid < 1) grid = 1;

    asl_build<<<(2 * TBL + C + 255) / 256, 256>>>(cat, C);
    asl_row_kernel<<<grid, 256>>>(X, Y, cat, inm, C, B, (float*)d_out);
}